// round 10
// baseline (speedup 1.0000x reference)
#include <cuda_runtime.h>
#include <cstdint>

// ---------------------------------------------------------------------------
#define BATCH 16
#define SEQ_S 1024
#define SEQ_T 2048
#define DIM   512
#define CF    2560
#define MELD  1280

#define TBM 128
#define TBN 128
#define TBK 16
#define AST 20        // stride for [m][k] A tile (conflict-free pattern)
#define BST 20        // stride for [n][k] B tile (B_TR=1)
#define SKS 136       // stride for [k][n] B tile (B_TR=0) / [k][m] A (A_COL=1)
#define A_REGION 2560 // 128*20
#define BUF_FLOATS 5120
// static smem: 2 * 5120 * 4 = 40 KB, 2 CTAs/SM

// ---------------------------------------------------------------------------
__device__ float g_k  [BATCH * SEQ_S * DIM];
__device__ float g_v  [BATCH * SEQ_S * DIM];
__device__ float g_q  [BATCH * SEQ_T * DIM];
__device__ float g_att[(size_t)BATCH * SEQ_T * SEQ_S];
__device__ float g_val[BATCH * SEQ_T * DIM];

// ---------------------------------------------------------------------------
__device__ __forceinline__ int get_len(const void* lp, int b) {
    const long long* l8 = (const long long*)lp;
    long long v0 = l8[0];
    if (v0 >= 1 && v0 <= 0x7fffffffLL) return (int)l8[b];
    return ((const int*)lp)[b];
}
__device__ __forceinline__ float ftf32(float x) {
    uint32_t u;
    asm("cvt.rna.tf32.f32 %0, %1;" : "=r"(u) : "f"(x));
    return __uint_as_float(u);
}
__device__ __forceinline__ float4 ftf32_4(float4 v) {
    return make_float4(ftf32(v.x), ftf32(v.y), ftf32(v.z), ftf32(v.w));
}

// ---------------------------------------------------------------------------
// tf32 GEMM, 128x128x16 tiles, 256 thr (2x4 warps, 64x32 warp tile),
// double-buffered. Transpose-free smem layouts:
//   A_COL=0: A tile stored [m][k] stride 20 (STS.128 + LDS conflict-free)
//   A_COL=1: A stored [K,M] in gmem -> smem [k][m] stride 136 (as before)
//   B_TR=1:  B tile stored [n][k] stride 20
//   B_TR=0:  B tile stored [k][n] stride 136 (as before)
//   EPI  : 0 +bias; 1 *scale; 2 none; 3 mel transposed store (+bias)
// ---------------------------------------------------------------------------
template<int A_COL, int B_TR, int EPI>
__global__ __launch_bounds__(256, 2)
void gemm_tf32(const float* __restrict__ Aall, int lda, long long strideA,
               const float* __restrict__ Ball, int ldb, long long strideB,
               const float* __restrict__ bias,
               float* __restrict__ Call, int ldc, long long strideC,
               int Kdim, float scale) {
    __shared__ __align__(16) float smem[2 * BUF_FLOATS];

    const int z = blockIdx.z;
    const float* A  = Aall + (size_t)z * strideA;
    const float* Bp = Ball + (size_t)z * strideB;
    float* C = Call + (size_t)z * strideC;

    const int bm = blockIdx.y * TBM;
    const int bn = blockIdx.x * TBN;

    const int tid = threadIdx.x;
    const int warp = tid >> 5, lane = tid & 31;
    const int wm = warp & 1, wn = warp >> 1;
    const int g = lane >> 2, tg = lane & 3;

    // conflict-free row/col mapping for stride-20 tiles
    const int r8  = (warp << 3) + (lane & 7);       // 0..63
    const int c4a = ((lane >> 3) & 3) << 2;         // {0,4,8,12}

    float4 acc[4][4];
    #pragma unroll
    for (int i = 0; i < 4; i++)
        #pragma unroll
        for (int j = 0; j < 4; j++) acc[i][j] = make_float4(0.f, 0.f, 0.f, 0.f);

    float4 ra[2], rb[2];

    // ---- global load of one k-slice into registers ----
#define LDG_TILE(K0)                                                           \
    {                                                                          \
        if (A_COL == 0) {                                                      \
            ra[0] = *(const float4*)(A + (size_t)(bm + r8) * lda + (K0) + c4a);\
            ra[1] = *(const float4*)(A + (size_t)(bm + r8 + 64) * lda + (K0) + c4a); \
        } else {                                                               \
            int kr = tid >> 4, m4 = (tid & 15) << 2;                           \
            ra[0] = *(const float4*)(A + (size_t)((K0) + kr) * lda + bm + m4); \
            ra[1] = *(const float4*)(A + (size_t)((K0) + kr) * lda + bm + m4 + 64); \
        }                                                                      \
        if (B_TR == 0) {                                                       \
            int kr = tid >> 5, n4 = (tid & 31) << 2;                           \
            rb[0] = *(const float4*)(Bp + (size_t)((K0) + kr) * ldb + bn + n4);\
            rb[1] = *(const float4*)(Bp + (size_t)((K0) + kr + 8) * ldb + bn + n4); \
        } else {                                                               \
            rb[0] = *(const float4*)(Bp + (size_t)(bn + r8) * ldb + (K0) + c4a);\
            rb[1] = *(const float4*)(Bp + (size_t)(bn + r8 + 64) * ldb + (K0) + c4a); \
        }                                                                      \
    }

    // ---- store staged registers into smem (all STS.128, conflict-free) ----
#define STS_TILE(DST)                                                          \
    {                                                                          \
        float* As_ = (DST);                                                    \
        float* Bs_ = (DST) + A_REGION;                                         \
        if (A_COL == 0) {                                                      \
            *(float4*)(As_ + (r8)      * AST + c4a) = ftf32_4(ra[0]);          \
            *(float4*)(As_ + (r8 + 64) * AST + c4a) = ftf32_4(ra[1]);          \
        } else {                                                               \
            int kr = tid >> 4, m4 = (tid & 15) << 2;                           \
            *(float4*)(As_ + kr * SKS + m4)      = ftf32_4(ra[0]);             \
            *(float4*)(As_ + kr * SKS + m4 + 64) = ftf32_4(ra[1]);             \
        }                                                                      \
        if (B_TR == 0) {                                                       \
            int kr = tid >> 5, n4 = (tid & 31) << 2;                           \
            *(float4*)(Bs_ + kr * SKS + n4)       = ftf32_4(rb[0]);            \
            *(float4*)(Bs_ + (kr + 8) * SKS + n4) = ftf32_4(rb[1]);            \
        } else {                                                               \
            *(float4*)(Bs_ + (r8)      * BST + c4a) = ftf32_4(rb[0]);          \
            *(float4*)(Bs_ + (r8 + 64) * BST + c4a) = ftf32_4(rb[1]);          \
        }                                                                      \
    }

    const int nk = Kdim >> 4;

    LDG_TILE(0);
    STS_TILE(smem);
    __syncthreads();

    for (int ks = 0; ks < nk; ks++) {
        const float* As = smem + (ks & 1) * BUF_FLOATS;
        const float* Bs = As + A_REGION;

        if (ks + 1 < nk) LDG_TILE((ks + 1) << 4);

        #pragma unroll
        for (int kk = 0; kk < TBK; kk += 8) {
            uint32_t af[4][4], bf[4][2];
            #pragma unroll
            for (int mi = 0; mi < 4; mi++) {
                int m0 = wm * 64 + mi * 16;
                if (A_COL == 0) {
                    af[mi][0] = __float_as_uint(As[(m0 + g)     * AST + kk + tg]);
                    af[mi][1] = __float_as_uint(As[(m0 + g + 8) * AST + kk + tg]);
                    af[mi][2] = __float_as_uint(As[(m0 + g)     * AST + kk + tg + 4]);
                    af[mi][3] = __float_as_uint(As[(m0 + g + 8) * AST + kk + tg + 4]);
                } else {
                    af[mi][0] = __float_as_uint(As[(kk + tg)     * SKS + m0 + g]);
                    af[mi][1] = __float_as_uint(As[(kk + tg)     * SKS + m0 + g + 8]);
                    af[mi][2] = __float_as_uint(As[(kk + tg + 4) * SKS + m0 + g]);
                    af[mi][3] = __float_as_uint(As[(kk + tg + 4) * SKS + m0 + g + 8]);
                }
            }
            #pragma unroll
            for (int ni = 0; ni < 4; ni++) {
                int n0 = wn * 32 + ni * 8;
                if (B_TR == 0) {
                    bf[ni][0] = __float_as_uint(Bs[(kk + tg)     * SKS + n0 + g]);
                    bf[ni][1] = __float_as_uint(Bs[(kk + tg + 4) * SKS + n0 + g]);
                } else {
                    bf[ni][0] = __float_as_uint(Bs[(n0 + g) * BST + kk + tg]);
                    bf[ni][1] = __float_as_uint(Bs[(n0 + g) * BST + kk + tg + 4]);
                }
            }
            #pragma unroll
            for (int mi = 0; mi < 4; mi++)
                #pragma unroll
                for (int ni = 0; ni < 4; ni++)
                    asm volatile(
                        "mma.sync.aligned.m16n8k8.row.col.f32.tf32.tf32.f32 "
                        "{%0,%1,%2,%3}, {%4,%5,%6,%7}, {%8,%9}, {%0,%1,%2,%3};\n"
                        : "+f"(acc[mi][ni].x), "+f"(acc[mi][ni].y),
                          "+f"(acc[mi][ni].z), "+f"(acc[mi][ni].w)
                        : "r"(af[mi][0]), "r"(af[mi][1]),
                          "r"(af[mi][2]), "r"(af[mi][3]),
                          "r"(bf[ni][0]), "r"(bf[ni][1]));
        }

        if (ks + 1 < nk) {
            STS_TILE(smem + ((ks + 1) & 1) * BUF_FLOATS);
            __syncthreads();
        }
    }

    // ---- epilogue ----
    if (EPI != 3) {
        #pragma unroll
        for (int mi = 0; mi < 4; mi++) {
            #pragma unroll
            for (int ni = 0; ni < 4; ni++) {
                int row = bm + wm * 64 + mi * 16 + g;
                int col = bn + wn * 32 + ni * 8 + 2 * tg;
                float4 a = acc[mi][ni];
                if (EPI == 0) {
                    float b0 = bias[col], b1 = bias[col + 1];
                    a.x += b0; a.y += b1; a.z += b0; a.w += b1;
                } else if (EPI == 1) {
                    a.x *= scale; a.y *= scale; a.z *= scale; a.w *= scale;
                }
                C[(size_t)row * ldc + col]           = a.x;
                C[(size_t)row * ldc + col + 1]       = a.y;
                C[(size_t)(row + 8) * ldc + col]     = a.z;
                C[(size_t)(row + 8) * ldc + col + 1] = a.w;
            }
        }
    } else {
        // mel: out[b, n%64, n/64, t]; stage 32-col chunks via smem transpose
        float* sc = smem;  // 32 x 132 = 4224 floats
        #pragma unroll 1
        for (int p = 0; p < 4; p++) {
            __syncthreads();
            if (wn == p) {
                #pragma unroll
                for (int mi = 0; mi < 4; mi++) {
                    #pragma unroll
                    for (int ni = 0; ni < 4; ni++) {
                        int ml = wm * 64 + mi * 16 + g;
                        int nl = ni * 8 + 2 * tg;
                        int ncol = bn + p * 32 + nl;
                        float b0 = bias[ncol], b1 = bias[ncol + 1];
                        float4 a = acc[mi][ni];
                        sc[nl * 132 + ml]           = a.x + b0;
                        sc[(nl + 1) * 132 + ml]     = a.y + b1;
                        sc[nl * 132 + ml + 8]       = a.z + b0;
                        sc[(nl + 1) * 132 + ml + 8] = a.w + b1;
                    }
                }
            }
            __syncthreads();
            int nl = tid >> 3, mq = (tid & 7) << 2;
            int ncol = bn + p * 32 + nl;
            size_t obase = ((size_t)z * 1280 + (size_t)(ncol & 63) * 20 + (ncol >> 6))
                           * (size_t)SEQ_T;
            #pragma unroll
            for (int it = 0; it < 4; it++) {
                int m = mq + it * 32;
                float4 v = *(float4*)(sc + nl * 132 + m);
                *(float4*)(Call + obase + bm + m) = v;
            }
        }
    }
#undef LDG_TILE
#undef STS_TILE
}

// ---------------------------------------------------------------------------
__global__ void softmax_kernel(const void* __restrict__ lengths) {
    int row = blockIdx.x;
    int b = row >> 11;
    float* p = g_att + (size_t)row * SEQ_S;
    int len = get_len(lengths, b);
    int tid = threadIdx.x;

    float4 x = ((const float4*)p)[tid];
    int s0 = tid * 4;
    __shared__ float red_m[8], red_s[8];

    float m = -1e30f;
    if (s0 + 0 < len) m = fmaxf(m, x.x);
    if (s0 + 1 < len) m = fmaxf(m, x.y);
    if (s0 + 2 < len) m = fmaxf(m, x.z);
    if (s0 + 3 < len) m = fmaxf(m, x.w);
    #pragma unroll
    for (int o = 16; o > 0; o >>= 1) m = fmaxf(m, __shfl_xor_sync(0xffffffffu, m, o));
    if ((tid & 31) == 0) red_m[tid >> 5] = m;
    __syncthreads();
    if (tid < 32) {
        float mm = (tid < 8) ? red_m[tid] : -1e30f;
        #pragma unroll
        for (int o = 4; o > 0; o >>= 1) mm = fmaxf(mm, __shfl_xor_sync(0xffffffffu, mm, o));
        if (tid == 0) red_m[0] = mm;
    }
    __syncthreads();
    m = red_m[0];

    float e0 = (s0 + 0 < len) ? __expf(x.x - m) : 0.f;
    float e1 = (s0 + 1 < len) ? __expf(x.y - m) : 0.f;
    float e2 = (s0 + 2 < len) ? __expf(x.z - m) : 0.f;
    float e3 = (s0 + 3 < len) ? __expf(x.w - m) : 0.f;
    float s = e0 + e1 + e2 + e3;
    #pragma unroll
    for (int o = 16; o > 0; o >>= 1) s += __shfl_xor_sync(0xffffffffu, s, o);
    if ((tid & 31) == 0) red_s[tid >> 5] = s;
    __syncthreads();
    if (tid < 32) {
        float ss = (tid < 8) ? red_s[tid] : 0.f;
        #pragma unroll
        for (int o = 4; o > 0; o >>= 1) ss += __shfl_xor_sync(0xffffffffu, ss, o);
        if (tid == 0) red_s[0] = ss;
    }
    __syncthreads();
    float inv = 1.0f / red_s[0];
    ((float4*)p)[tid] = make_float4(e0 * inv, e1 * inv, e2 * inv, e3 * inv);
}

// ---------------------------------------------------------------------------
extern "C" void kernel_launch(void* const* d_in, const int* in_sizes, int n_in,
                              void* d_out, int out_size) {
    const float* ph   = (const float*)d_in[0];
    const float* g    = (const float*)d_in[1];
    const void*  lens = d_in[2];
    const float* Wk   = (const float*)d_in[3];
    const float* bk   = (const float*)d_in[4];
    const float* Wv   = (const float*)d_in[5];
    const float* bv   = (const float*)d_in[6];
    const float* Wq   = (const float*)d_in[7];
    const float* bq   = (const float*)d_in[8];
    const float* Wmel = (const float*)d_in[9];
    const float* bmel = (const float*)d_in[10];
    float* out = (float*)d_out;

    float* dk;   cudaGetSymbolAddress((void**)&dk,   g_k);
    float* dv;   cudaGetSymbolAddress((void**)&dv,   g_v);
    float* dq;   cudaGetSymbolAddress((void**)&dq,   g_q);
    float* datt; cudaGetSymbolAddress((void**)&datt, g_att);
    float* dval; cudaGetSymbolAddress((void**)&dval, g_val);

    const float scale = 0.04419417382415922f;  // 1/sqrt(512)
    dim3 blk(256);

    gemm_tf32<0,0,0><<<dim3(4, 128, 1), blk>>>(ph, DIM, 0, Wk, DIM, 0, bk,
                                               dk, DIM, 0, DIM, 1.f);
    gemm_tf32<0,0,0><<<dim3(4, 128, 1), blk>>>(ph, DIM, 0, Wv, DIM, 0, bv,
                                               dv, DIM, 0, DIM, 1.f);
    gemm_tf32<1,0,0><<<dim3(4, 16, BATCH), blk>>>(g, SEQ_T, (long long)CF * SEQ_T,
                                                  Wq, DIM, 0, bq,
                                                  dq, DIM, (long long)SEQ_T * DIM,
                                                  CF, 1.f);
    gemm_tf32<0,1,1><<<dim3(8, 16, BATCH), blk>>>(dq, DIM, (long long)SEQ_T * DIM,
                                                  dk, DIM, (long long)SEQ_S * DIM,
                                                  nullptr,
                                                  datt, SEQ_S, (long long)SEQ_T * SEQ_S,
                                                  DIM, scale);
    softmax_kernel<<<BATCH * SEQ_T, 256>>>(lens);
    gemm_tf32<0,0,2><<<dim3(4, 16, BATCH), blk>>>(datt, SEQ_S, (long long)SEQ_T * SEQ_S,
                                                  dv, DIM, (long long)SEQ_S * DIM,
                                                  nullptr,
                                                  dval, DIM, (long long)SEQ_T * DIM,
                                                  SEQ_S, 1.f);
    gemm_tf32<0,0,3><<<dim3(10, 16, BATCH), blk>>>(dval, DIM, (long long)SEQ_T * DIM,
                                                   Wmel, MELD, 0, bmel,
                                                   out, 0, 0, DIM, 1.f);
}

// round 11
// speedup vs baseline: 1.5158x; 1.5158x over previous
#include <cuda_runtime.h>
#include <cstdint>

// ---------------------------------------------------------------------------
#define BATCH 16
#define SEQ_S 1024
#define SEQ_T 2048
#define DIM   512
#define CF    2560
#define MELD  1280

#define TBM 128
#define TBN 128
#define TBK 16
#define SAS 136      // smem stride (floats): conflict-free frag LDS (R5 proven)
#define SBS 136
#define BUF_FLOATS (TBK * SAS + TBK * SBS)   // 4352 floats per buffer

// ---------------------------------------------------------------------------
__device__ float g_k  [BATCH * SEQ_S * DIM];
__device__ float g_v  [BATCH * SEQ_S * DIM];
__device__ float g_q  [BATCH * SEQ_T * DIM];
__device__ float g_att[(size_t)BATCH * SEQ_T * SEQ_S];
__device__ float g_val[BATCH * SEQ_T * DIM];

// ---------------------------------------------------------------------------
__device__ __forceinline__ int get_len(const void* lp, int b) {
    const long long* l8 = (const long long*)lp;
    long long v0 = l8[0];
    if (v0 >= 1 && v0 <= 0x7fffffffLL) return (int)l8[b];
    return ((const int*)lp)[b];
}
__device__ __forceinline__ float ftf32(float x) {
    uint32_t u;
    asm("cvt.rna.tf32.f32 %0, %1;" : "=r"(u) : "f"(x));
    return __uint_as_float(u);
}
__device__ __forceinline__ float4 ftf32_4(float4 v) {
    return make_float4(ftf32(v.x), ftf32(v.y), ftf32(v.z), ftf32(v.w));
}

// ---------------------------------------------------------------------------
// tf32 GEMM, 128x128x16 tiles, 256 thr (2x4 warps, 64x32 warp tile),
// double-buffered (R5-proven layouts; addresses affine).
//   A_COL: 0 -> A [M,K] row-major; 1 -> A stored [K,M]
//   B_TR : 0 -> B [K,N]; 1 -> B [N,K]
//   EPI  : 0 +bias; 1 *scale; 2 none; 3 mel transposed store (+bias)
//   TRIM : 0 none | 1 exit if A-row block >= len (kv; batch = bm>>10)
//          2 exit if bn >= len[z] (scores) | 3 bound K at ceil16(len[z]) (value)
// ---------------------------------------------------------------------------
template<int A_COL, int B_TR, int EPI, int TRIM>
__global__ __launch_bounds__(256, 2)
void gemm_tf32(const float* __restrict__ Aall, int lda, long long strideA,
               const float* __restrict__ Ball, int ldb, long long strideB,
               const float* __restrict__ bias,
               float* __restrict__ Call, int ldc, long long strideC,
               int Kdim, float scale, const void* __restrict__ lens) {
    __shared__ __align__(16) float smem[2 * BUF_FLOATS];

    const int z = blockIdx.z;
    const int bm = blockIdx.y * TBM;
    const int bn = blockIdx.x * TBN;

    if (TRIM == 1) {
        int len = get_len(lens, bm >> 10);
        if ((bm & (SEQ_S - 1)) >= len) return;
    }
    if (TRIM == 2) {
        int len = get_len(lens, z);
        if (bn >= len) return;
    }
    int Keff = Kdim;
    if (TRIM == 3) {
        int len = get_len(lens, z);
        Keff = (len + 15) & ~15;           // >= 16, multiple of TBK
    }

    const float* A  = Aall + (size_t)z * strideA;
    const float* Bp = Ball + (size_t)z * strideB;
    float* C = Call + (size_t)z * strideC;

    const int tid = threadIdx.x;
    const int warp = tid >> 5, lane = tid & 31;
    const int wm = warp & 1, wn = warp >> 1;
    const int g = lane >> 2, tg = lane & 3;

    float4 acc[4][4];
    #pragma unroll
    for (int i = 0; i < 4; i++)
        #pragma unroll
        for (int j = 0; j < 4; j++) acc[i][j] = make_float4(0.f, 0.f, 0.f, 0.f);

    float4 ra[2], rb[2];

    // ---- global load of one k-slice into registers (coalesced float4) ----
#define LDG_TILE(K0)                                                           \
    {                                                                          \
        if (A_COL == 0) {                                                      \
            int r = tid >> 2, c4 = (tid & 3) << 2;                             \
            ra[0] = *(const float4*)(A + (size_t)(bm + r) * lda + (K0) + c4);  \
            ra[1] = *(const float4*)(A + (size_t)(bm + r + 64) * lda + (K0) + c4); \
        } else {                                                               \
            int kr = tid >> 4, m4 = (tid & 15) << 2;                           \
            ra[0] = *(const float4*)(A + (size_t)((K0) + kr) * lda + bm + m4); \
            ra[1] = *(const float4*)(A + (size_t)((K0) + kr) * lda + bm + m4 + 64); \
        }                                                                      \
        if (B_TR == 0) {                                                       \
            int kr = tid >> 5, n4 = (tid & 31) << 2;                           \
            rb[0] = *(const float4*)(Bp + (size_t)((K0) + kr) * ldb + bn + n4);\
            rb[1] = *(const float4*)(Bp + (size_t)((K0) + kr + 8) * ldb + bn + n4); \
        } else {                                                               \
            int r = tid >> 2, c4 = (tid & 3) << 2;                             \
            rb[0] = *(const float4*)(Bp + (size_t)(bn + r) * ldb + (K0) + c4); \
            rb[1] = *(const float4*)(Bp + (size_t)(bn + r + 64) * ldb + (K0) + c4); \
        }                                                                      \
    }

    // ---- store staged registers into smem tile (R5 layout, affine) ----
#define STS_TILE(DST)                                                          \
    {                                                                          \
        float* As_ = (DST);                                                    \
        float* Bs_ = (DST) + TBK * SAS;                                        \
        if (A_COL == 0) {                                                      \
            int r = tid >> 2, c4 = (tid & 3) << 2;                             \
            _Pragma("unroll")                                                  \
            for (int p = 0; p < 2; p++) {                                      \
                int row = r + (p << 6);                                        \
                const float* v = &ra[p].x;                                     \
                _Pragma("unroll")                                              \
                for (int j = 0; j < 4; j++)                                    \
                    As_[(c4 + j) * SAS + row] = ftf32(v[j]);                   \
            }                                                                  \
        } else {                                                               \
            int kr = tid >> 4, m4 = (tid & 15) << 2;                           \
            *(float4*)(As_ + kr * SAS + m4)      = ftf32_4(ra[0]);             \
            *(float4*)(As_ + kr * SAS + m4 + 64) = ftf32_4(ra[1]);             \
        }                                                                      \
        if (B_TR == 0) {                                                       \
            int kr = tid >> 5, n4 = (tid & 31) << 2;                           \
            *(float4*)(Bs_ + kr * SBS + n4)       = ftf32_4(rb[0]);            \
            *(float4*)(Bs_ + (kr + 8) * SBS + n4) = ftf32_4(rb[1]);            \
        } else {                                                               \
            int r = tid >> 2, c4 = (tid & 3) << 2;                             \
            _Pragma("unroll")                                                  \
            for (int p = 0; p < 2; p++) {                                      \
                int n = r + (p << 6);                                          \
                const float* v = &rb[p].x;                                     \
                _Pragma("unroll")                                              \
                for (int j = 0; j < 4; j++)                                    \
                    Bs_[(c4 + j) * SBS + n] = ftf32(v[j]);                     \
            }                                                                  \
        }                                                                      \
    }

    const int nk = Keff >> 4;

    LDG_TILE(0);
    STS_TILE(smem);
    __syncthreads();

    for (int ks = 0; ks < nk; ks++) {
        const float* As = smem + (ks & 1) * BUF_FLOATS;
        const float* Bs = As + TBK * SAS;

        if (ks + 1 < nk) LDG_TILE((ks + 1) << 4);

        #pragma unroll
        for (int kk = 0; kk < TBK; kk += 8) {
            uint32_t af[4][4], bf[4][2];
            #pragma unroll
            for (int mi = 0; mi < 4; mi++) {
                int m0 = wm * 64 + mi * 16;
                af[mi][0] = __float_as_uint(As[(kk + tg) * SAS + m0 + g]);
                af[mi][1] = __float_as_uint(As[(kk + tg) * SAS + m0 + g + 8]);
                af[mi][2] = __float_as_uint(As[(kk + tg + 4) * SAS + m0 + g]);
                af[mi][3] = __float_as_uint(As[(kk + tg + 4) * SAS + m0 + g + 8]);
            }
            #pragma unroll
            for (int ni = 0; ni < 4; ni++) {
                int n0 = wn * 32 + ni * 8;
                bf[ni][0] = __float_as_uint(Bs[(kk + tg) * SBS + n0 + g]);
                bf[ni][1] = __float_as_uint(Bs[(kk + tg + 4) * SBS + n0 + g]);
            }
            #pragma unroll
            for (int mi = 0; mi < 4; mi++)
                #pragma unroll
                for (int ni = 0; ni < 4; ni++)
                    asm volatile(
                        "mma.sync.aligned.m16n8k8.row.col.f32.tf32.tf32.f32 "
                        "{%0,%1,%2,%3}, {%4,%5,%6,%7}, {%8,%9}, {%0,%1,%2,%3};\n"
                        : "+f"(acc[mi][ni].x), "+f"(acc[mi][ni].y),
                          "+f"(acc[mi][ni].z), "+f"(acc[mi][ni].w)
                        : "r"(af[mi][0]), "r"(af[mi][1]),
                          "r"(af[mi][2]), "r"(af[mi][3]),
                          "r"(bf[ni][0]), "r"(bf[ni][1]));
        }

        if (ks + 1 < nk) {
            STS_TILE(smem + ((ks + 1) & 1) * BUF_FLOATS);
            __syncthreads();
        }
    }

    // ---- epilogue ----
    if (EPI != 3) {
        #pragma unroll
        for (int mi = 0; mi < 4; mi++) {
            #pragma unroll
            for (int ni = 0; ni < 4; ni++) {
                int row = bm + wm * 64 + mi * 16 + g;
                int col = bn + wn * 32 + ni * 8 + 2 * tg;
                float4 a = acc[mi][ni];
                if (EPI == 0) {
                    float b0 = bias[col], b1 = bias[col + 1];
                    a.x += b0; a.y += b1; a.z += b0; a.w += b1;
                } else if (EPI == 1) {
                    a.x *= scale; a.y *= scale; a.z *= scale; a.w *= scale;
                }
                C[(size_t)row * ldc + col]           = a.x;
                C[(size_t)row * ldc + col + 1]       = a.y;
                C[(size_t)(row + 8) * ldc + col]     = a.z;
                C[(size_t)(row + 8) * ldc + col + 1] = a.w;
            }
        }
    } else {
        // mel: out[b, n%64, n/64, t]; stage 32-col chunks via smem transpose
        float* sc = smem;  // 32 x 132 = 4224 floats (fits in buffers)
        #pragma unroll 1
        for (int p = 0; p < 4; p++) {
            __syncthreads();
            if (wn == p) {
                #pragma unroll
                for (int mi = 0; mi < 4; mi++) {
                    #pragma unroll
                    for (int ni = 0; ni < 4; ni++) {
                        int ml = wm * 64 + mi * 16 + g;
                        int nl = ni * 8 + 2 * tg;
                        int ncol = bn + p * 32 + nl;
                        float b0 = bias[ncol], b1 = bias[ncol + 1];
                        float4 a = acc[mi][ni];
                        sc[nl * 132 + ml]           = a.x + b0;
                        sc[(nl + 1) * 132 + ml]     = a.y + b1;
                        sc[nl * 132 + ml + 8]       = a.z + b0;
                        sc[(nl + 1) * 132 + ml + 8] = a.w + b1;
                    }
                }
            }
            __syncthreads();
            int nl = tid >> 3, mq = (tid & 7) << 2;
            int ncol = bn + p * 32 + nl;
            size_t obase = ((size_t)z * 1280 + (size_t)(ncol & 63) * 20 + (ncol >> 6))
                           * (size_t)SEQ_T;
            #pragma unroll
            for (int it = 0; it < 4; it++) {
                int m = mq + it * 32;
                float4 v = *(float4*)(sc + nl * 132 + m);
                *(float4*)(Call + obase + bm + m) = v;
            }
        }
    }
#undef LDG_TILE
#undef STS_TILE
}

// ---------------------------------------------------------------------------
// masked softmax; only touches s < ceil16(len) (value kernel reads no further)
// ---------------------------------------------------------------------------
__global__ void softmax_kernel(const void* __restrict__ lengths) {
    int row = blockIdx.x;
    int b = row >> 11;
    float* p = g_att + (size_t)row * SEQ_S;
    int len = get_len(lengths, b);
    int spad = (len + 15) & ~15;
    int tid = threadIdx.x;
    int s0 = tid * 4;

    float4 x = make_float4(0.f, 0.f, 0.f, 0.f);
    if (s0 < spad) x = ((const float4*)p)[tid];

    __shared__ float red_m[8], red_s[8];

    float m = -1e30f;
    if (s0 + 0 < len) m = fmaxf(m, x.x);
    if (s0 + 1 < len) m = fmaxf(m, x.y);
    if (s0 + 2 < len) m = fmaxf(m, x.z);
    if (s0 + 3 < len) m = fmaxf(m, x.w);
    #pragma unroll
    for (int o = 16; o > 0; o >>= 1) m = fmaxf(m, __shfl_xor_sync(0xffffffffu, m, o));
    if ((tid & 31) == 0) red_m[tid >> 5] = m;
    __syncthreads();
    if (tid < 32) {
        float mm = (tid < 8) ? red_m[tid] : -1e30f;
        #pragma unroll
        for (int o = 4; o > 0; o >>= 1) mm = fmaxf(mm, __shfl_xor_sync(0xffffffffu, mm, o));
        if (tid == 0) red_m[0] = mm;
    }
    __syncthreads();
    m = red_m[0];

    float e0 = (s0 + 0 < len) ? __expf(x.x - m) : 0.f;
    float e1 = (s0 + 1 < len) ? __expf(x.y - m) : 0.f;
    float e2 = (s0 + 2 < len) ? __expf(x.z - m) : 0.f;
    float e3 = (s0 + 3 < len) ? __expf(x.w - m) : 0.f;
    float s = e0 + e1 + e2 + e3;
    #pragma unroll
    for (int o = 16; o > 0; o >>= 1) s += __shfl_xor_sync(0xffffffffu, s, o);
    if ((tid & 31) == 0) red_s[tid >> 5] = s;
    __syncthreads();
    if (tid < 32) {
        float ss = (tid < 8) ? red_s[tid] : 0.f;
        #pragma unroll
        for (int o = 4; o > 0; o >>= 1) ss += __shfl_xor_sync(0xffffffffu, ss, o);
        if (tid == 0) red_s[0] = ss;
    }
    __syncthreads();
    float inv = 1.0f / red_s[0];

    if (s0 < spad)
        ((float4*)p)[tid] = make_float4(e0 * inv, e1 * inv, e2 * inv, e3 * inv);
}

// ---------------------------------------------------------------------------
extern "C" void kernel_launch(void* const* d_in, const int* in_sizes, int n_in,
                              void* d_out, int out_size) {
    const float* ph   = (const float*)d_in[0];
    const float* g    = (const float*)d_in[1];
    const void*  lens = d_in[2];
    const float* Wk   = (const float*)d_in[3];
    const float* bk   = (const float*)d_in[4];
    const float* Wv   = (const float*)d_in[5];
    const float* bv   = (const float*)d_in[6];
    const float* Wq   = (const float*)d_in[7];
    const float* bq   = (const float*)d_in[8];
    const float* Wmel = (const float*)d_in[9];
    const float* bmel = (const float*)d_in[10];
    float* out = (float*)d_out;

    float* dk;   cudaGetSymbolAddress((void**)&dk,   g_k);
    float* dv;   cudaGetSymbolAddress((void**)&dv,   g_v);
    float* dq;   cudaGetSymbolAddress((void**)&dq,   g_q);
    float* datt; cudaGetSymbolAddress((void**)&datt, g_att);
    float* dval; cudaGetSymbolAddress((void**)&dval, g_val);

    const float scale = 0.04419417382415922f;  // 1/sqrt(512)
    dim3 blk(256);

    // k/v projections: skip M-blocks fully beyond len (TRIM=1)
    gemm_tf32<0,0,0,1><<<dim3(4, 128, 1), blk>>>(ph, DIM, 0, Wk, DIM, 0, bk,
                                                 dk, DIM, 0, DIM, 1.f, lens);
    gemm_tf32<0,0,0,1><<<dim3(4, 128, 1), blk>>>(ph, DIM, 0, Wv, DIM, 0, bv,
                                                 dv, DIM, 0, DIM, 1.f, lens);
    // q projection (full)
    gemm_tf32<1,0,0,0><<<dim3(4, 16, BATCH), blk>>>(g, SEQ_T, (long long)CF * SEQ_T,
                                                    Wq, DIM, 0, bq,
                                                    dq, DIM, (long long)SEQ_T * DIM,
                                                    CF, 1.f, lens);
    // scores: skip N-blocks beyond len (TRIM=2)
    gemm_tf32<0,1,1,2><<<dim3(8, 16, BATCH), blk>>>(dq, DIM, (long long)SEQ_T * DIM,
                                                    dk, DIM, (long long)SEQ_S * DIM,
                                                    nullptr,
                                                    datt, SEQ_S, (long long)SEQ_T * SEQ_S,
                                                    DIM, scale, lens);
    softmax_kernel<<<BATCH * SEQ_T, 256>>>(lens);
    // value: K bounded at ceil16(len) (TRIM=3)
    gemm_tf32<0,0,2,3><<<dim3(4, 16, BATCH), blk>>>(datt, SEQ_S, (long long)SEQ_T * SEQ_S,
                                                    dv, DIM, (long long)SEQ_S * DIM,
                                                    nullptr,
                                                    dval, DIM, (long long)SEQ_T * DIM,
                                                    SEQ_S, 1.f, lens);
    // mel projection + transposed store (full)
    gemm_tf32<0,0,3,0><<<dim3(10, 16, BATCH), blk>>>(dval, DIM, (long long)SEQ_T * DIM,
                                                     Wmel, MELD, 0, bmel,
                                                     out, 0, 0, DIM, 1.f, lens);
}

// round 12
// speedup vs baseline: 1.6134x; 1.0643x over previous
#include <cuda_runtime.h>
#include <cstdint>

// ---------------------------------------------------------------------------
#define BATCH 16
#define SEQ_S 1024
#define SEQ_T 2048
#define DIM   512
#define CF    2560
#define MELD  1280

#define TBM 128
#define TBN 128
#define TBK 16
#define SAS 136      // smem stride (floats): conflict-free frag LDS (R5 proven)
#define SBS 136
#define BUF_FLOATS (TBK * SAS + TBK * SBS)   // 4352 floats per buffer

// ---------------------------------------------------------------------------
__device__ float g_kT [BATCH * DIM * SEQ_S];     // k transposed [b][d][s]
__device__ float g_v  [BATCH * SEQ_S * DIM];
__device__ float g_qT [BATCH * DIM * SEQ_T];     // q transposed [b][d][t]
__device__ float g_att[(size_t)BATCH * SEQ_T * SEQ_S];
__device__ float g_valT[BATCH * DIM * SEQ_T];    // value transposed [b][d][t]

// ---------------------------------------------------------------------------
__device__ __forceinline__ int get_len(const void* lp, int b) {
    const long long* l8 = (const long long*)lp;
    long long v0 = l8[0];
    if (v0 >= 1 && v0 <= 0x7fffffffLL) return (int)l8[b];
    return ((const int*)lp)[b];
}
__device__ __forceinline__ float ftf32(float x) {
    uint32_t u;
    asm("cvt.rna.tf32.f32 %0, %1;" : "=r"(u) : "f"(x));
    return __uint_as_float(u);
}
__device__ __forceinline__ float4 ftf32_4(float4 v) {
    return make_float4(ftf32(v.x), ftf32(v.y), ftf32(v.z), ftf32(v.w));
}

// ---------------------------------------------------------------------------
// tf32 GEMM, 128x128x16 tiles, 256 thr (2x4 warps, 64x32 warp tile),
// double-buffered (R5-proven layouts; addresses affine).
//   A_COL: 0 -> A [M,K] row-major; 1 -> A stored [K,M]
//   B_TR : 0 -> B [K,N]; 1 -> B [N,K]
//   EPI  : 0 +bias rowmajor | 1 *scale rowmajor | 2 none rowmajor
//          3 +bias mel-transposed | 4 (+bias if nonnull) CT z-batched store
//          5 +bias kT store (batch from bm)
//   TRIM : 0 none | 1 exit if A-row block >= len (kv; batch = bm>>10)
//          2 exit if bn >= len[z] (scores) | 3 bound K at ceil16(len[z]) (value)
// ---------------------------------------------------------------------------
template<int A_COL, int B_TR, int EPI, int TRIM>
__global__ __launch_bounds__(256, 2)
void gemm_tf32(const float* __restrict__ Aall, int lda, long long strideA,
               const float* __restrict__ Ball, int ldb, long long strideB,
               const float* __restrict__ bias,
               float* __restrict__ Call, int ldc, long long strideC,
               int Kdim, float scale, const void* __restrict__ lens) {
    __shared__ __align__(16) float smem[2 * BUF_FLOATS];

    const int z = blockIdx.z;
    const int bm = blockIdx.y * TBM;
    const int bn = blockIdx.x * TBN;

    if (TRIM == 1) {
        int len = get_len(lens, bm >> 10);
        if ((bm & (SEQ_S - 1)) >= len) return;
    }
    if (TRIM == 2) {
        int len = get_len(lens, z);
        if (bn >= len) return;
    }
    int Keff = Kdim;
    if (TRIM == 3) {
        int len = get_len(lens, z);
        Keff = (len + 15) & ~15;           // >= 16, multiple of TBK
    }

    const float* A  = Aall + (size_t)z * strideA;
    const float* Bp = Ball + (size_t)z * strideB;
    float* C = Call + (size_t)z * strideC;

    const int tid = threadIdx.x;
    const int warp = tid >> 5, lane = tid & 31;
    const int wm = warp & 1, wn = warp >> 1;
    const int g = lane >> 2, tg = lane & 3;

    float4 acc[4][4];
    #pragma unroll
    for (int i = 0; i < 4; i++)
        #pragma unroll
        for (int j = 0; j < 4; j++) acc[i][j] = make_float4(0.f, 0.f, 0.f, 0.f);

    float4 ra[2], rb[2];

    // ---- global load of one k-slice into registers (coalesced float4) ----
#define LDG_TILE(K0)                                                           \
    {                                                                          \
        if (A_COL == 0) {                                                      \
            int r = tid >> 2, c4 = (tid & 3) << 2;                             \
            ra[0] = *(const float4*)(A + (size_t)(bm + r) * lda + (K0) + c4);  \
            ra[1] = *(const float4*)(A + (size_t)(bm + r + 64) * lda + (K0) + c4); \
        } else {                                                               \
            int kr = tid >> 4, m4 = (tid & 15) << 2;                           \
            ra[0] = *(const float4*)(A + (size_t)((K0) + kr) * lda + bm + m4); \
            ra[1] = *(const float4*)(A + (size_t)((K0) + kr) * lda + bm + m4 + 64); \
        }                                                                      \
        if (B_TR == 0) {                                                       \
            int kr = tid >> 5, n4 = (tid & 31) << 2;                           \
            rb[0] = *(const float4*)(Bp + (size_t)((K0) + kr) * ldb + bn + n4);\
            rb[1] = *(const float4*)(Bp + (size_t)((K0) + kr + 8) * ldb + bn + n4); \
        } else {                                                               \
            int r = tid >> 2, c4 = (tid & 3) << 2;                             \
            rb[0] = *(const float4*)(Bp + (size_t)(bn + r) * ldb + (K0) + c4); \
            rb[1] = *(const float4*)(Bp + (size_t)(bn + r + 64) * ldb + (K0) + c4); \
        }                                                                      \
    }

    // ---- store staged registers into smem tile (R5 layout, affine) ----
#define STS_TILE(DST)                                                          \
    {                                                                          \
        float* As_ = (DST);                                                    \
        float* Bs_ = (DST) + TBK * SAS;                                        \
        if (A_COL == 0) {                                                      \
            int r = tid >> 2, c4 = (tid & 3) << 2;                             \
            _Pragma("unroll")                                                  \
            for (int p = 0; p < 2; p++) {                                      \
                int row = r + (p << 6);                                        \
                const float* v = &ra[p].x;                                     \
                _Pragma("unroll")                                              \
                for (int j = 0; j < 4; j++)                                    \
                    As_[(c4 + j) * SAS + row] = ftf32(v[j]);                   \
            }                                                                  \
        } else {                                                               \
            int kr = tid >> 4, m4 = (tid & 15) << 2;                           \
            *(float4*)(As_ + kr * SAS + m4)      = ftf32_4(ra[0]);             \
            *(float4*)(As_ + kr * SAS + m4 + 64) = ftf32_4(ra[1]);             \
        }                                                                      \
        if (B_TR == 0) {                                                       \
            int kr = tid >> 5, n4 = (tid & 31) << 2;                           \
            *(float4*)(Bs_ + kr * SBS + n4)       = ftf32_4(rb[0]);            \
            *(float4*)(Bs_ + (kr + 8) * SBS + n4) = ftf32_4(rb[1]);            \
        } else {                                                               \
            int r = tid >> 2, c4 = (tid & 3) << 2;                             \
            _Pragma("unroll")                                                  \
            for (int p = 0; p < 2; p++) {                                      \
                int n = r + (p << 6);                                          \
                const float* v = &rb[p].x;                                     \
                _Pragma("unroll")                                              \
                for (int j = 0; j < 4; j++)                                    \
                    Bs_[(c4 + j) * SBS + n] = ftf32(v[j]);                     \
            }                                                                  \
        }                                                                      \
    }

    const int nk = Keff >> 4;

    LDG_TILE(0);
    STS_TILE(smem);
    __syncthreads();

    for (int ks = 0; ks < nk; ks++) {
        const float* As = smem + (ks & 1) * BUF_FLOATS;
        const float* Bs = As + TBK * SAS;

        if (ks + 1 < nk) LDG_TILE((ks + 1) << 4);

        #pragma unroll
        for (int kk = 0; kk < TBK; kk += 8) {
            uint32_t af[4][4], bf[4][2];
            #pragma unroll
            for (int mi = 0; mi < 4; mi++) {
                int m0 = wm * 64 + mi * 16;
                af[mi][0] = __float_as_uint(As[(kk + tg) * SAS + m0 + g]);
                af[mi][1] = __float_as_uint(As[(kk + tg) * SAS + m0 + g + 8]);
                af[mi][2] = __float_as_uint(As[(kk + tg + 4) * SAS + m0 + g]);
                af[mi][3] = __float_as_uint(As[(kk + tg + 4) * SAS + m0 + g + 8]);
            }
            #pragma unroll
            for (int ni = 0; ni < 4; ni++) {
                int n0 = wn * 32 + ni * 8;
                bf[ni][0] = __float_as_uint(Bs[(kk + tg) * SBS + n0 + g]);
                bf[ni][1] = __float_as_uint(Bs[(kk + tg + 4) * SBS + n0 + g]);
            }
            #pragma unroll
            for (int mi = 0; mi < 4; mi++)
                #pragma unroll
                for (int ni = 0; ni < 4; ni++)
                    asm volatile(
                        "mma.sync.aligned.m16n8k8.row.col.f32.tf32.tf32.f32 "
                        "{%0,%1,%2,%3}, {%4,%5,%6,%7}, {%8,%9}, {%0,%1,%2,%3};\n"
                        : "+f"(acc[mi][ni].x), "+f"(acc[mi][ni].y),
                          "+f"(acc[mi][ni].z), "+f"(acc[mi][ni].w)
                        : "r"(af[mi][0]), "r"(af[mi][1]),
                          "r"(af[mi][2]), "r"(af[mi][3]),
                          "r"(bf[ni][0]), "r"(bf[ni][1]));
        }

        if (ks + 1 < nk) {
            STS_TILE(smem + ((ks + 1) & 1) * BUF_FLOATS);
            __syncthreads();
        }
    }

    // ---- epilogue ----
    if (EPI <= 2) {
        #pragma unroll
        for (int mi = 0; mi < 4; mi++) {
            #pragma unroll
            for (int ni = 0; ni < 4; ni++) {
                int row = bm + wm * 64 + mi * 16 + g;
                int col = bn + wn * 32 + ni * 8 + 2 * tg;
                float4 a = acc[mi][ni];
                if (EPI == 0) {
                    float b0 = bias[col], b1 = bias[col + 1];
                    a.x += b0; a.y += b1; a.z += b0; a.w += b1;
                } else if (EPI == 1) {
                    a.x *= scale; a.y *= scale; a.z *= scale; a.w *= scale;
                }
                C[(size_t)row * ldc + col]           = a.x;
                C[(size_t)row * ldc + col + 1]       = a.y;
                C[(size_t)(row + 8) * ldc + col]     = a.z;
                C[(size_t)(row + 8) * ldc + col + 1] = a.w;
            }
        }
    } else {
        // staged transposed store: chunks of 32 n-cols via smem, float4 along m
        float* sc = smem;  // 32 x 132 = 4224 floats (fits in buffers)
        #pragma unroll 1
        for (int p = 0; p < 4; p++) {
            __syncthreads();
            if (wn == p) {
                #pragma unroll
                for (int mi = 0; mi < 4; mi++) {
                    #pragma unroll
                    for (int ni = 0; ni < 4; ni++) {
                        int ml = wm * 64 + mi * 16 + g;
                        int nl = ni * 8 + 2 * tg;
                        int ncol = bn + p * 32 + nl;
                        float b0 = 0.f, b1 = 0.f;
                        if (EPI != 4 || bias) {
                            b0 = bias[ncol]; b1 = bias[ncol + 1];
                        }
                        float4 a = acc[mi][ni];
                        sc[nl * 132 + ml]           = a.x + b0;
                        sc[(nl + 1) * 132 + ml]     = a.y + b1;
                        sc[nl * 132 + ml + 8]       = a.z + b0;
                        sc[(nl + 1) * 132 + ml + 8] = a.w + b1;
                    }
                }
            }
            __syncthreads();
            int nl = tid >> 3, mq = (tid & 7) << 2;
            int ncol = bn + p * 32 + nl;
            size_t obase;
            if (EPI == 3)
                obase = ((size_t)z * 1280 + (size_t)(ncol & 63) * 20 + (ncol >> 6))
                        * (size_t)SEQ_T + bm;
            else if (EPI == 4)
                obase = (size_t)z * strideC + (size_t)ncol * ldc + bm;
            else  // EPI == 5: kT[b][d][s], b derived from global row block
                obase = ((size_t)(bm >> 10) * DIM + ncol) * (size_t)SEQ_S
                        + (bm & (SEQ_S - 1));
            #pragma unroll
            for (int it = 0; it < 4; it++) {
                int m = mq + it * 32;
                float4 v = *(float4*)(sc + nl * 132 + m);
                *(float4*)(Call + obase + m) = v;
            }
        }
    }
#undef LDG_TILE
#undef STS_TILE
}

// ---------------------------------------------------------------------------
// masked softmax; only touches s < ceil16(len) (value kernel reads no further)
// ---------------------------------------------------------------------------
__global__ void softmax_kernel(const void* __restrict__ lengths) {
    int row = blockIdx.x;
    int b = row >> 11;
    float* p = g_att + (size_t)row * SEQ_S;
    int len = get_len(lengths, b);
    int spad = (len + 15) & ~15;
    int tid = threadIdx.x;
    int s0 = tid * 4;

    float4 x = make_float4(0.f, 0.f, 0.f, 0.f);
    if (s0 < spad) x = ((const float4*)p)[tid];

    __shared__ float red_m[8], red_s[8];

    float m = -1e30f;
    if (s0 + 0 < len) m = fmaxf(m, x.x);
    if (s0 + 1 < len) m = fmaxf(m, x.y);
    if (s0 + 2 < len) m = fmaxf(m, x.z);
    if (s0 + 3 < len) m = fmaxf(m, x.w);
    #pragma unroll
    for (int o = 16; o > 0; o >>= 1) m = fmaxf(m, __shfl_xor_sync(0xffffffffu, m, o));
    if ((tid & 31) == 0) red_m[tid >> 5] = m;
    __syncthreads();
    if (tid < 32) {
        float mm = (tid < 8) ? red_m[tid] : -1e30f;
        #pragma unroll
        for (int o = 4; o > 0; o >>= 1) mm = fmaxf(mm, __shfl_xor_sync(0xffffffffu, mm, o));
        if (tid == 0) red_m[0] = mm;
    }
    __syncthreads();
    m = red_m[0];

    float e0 = (s0 + 0 < len) ? __expf(x.x - m) : 0.f;
    float e1 = (s0 + 1 < len) ? __expf(x.y - m) : 0.f;
    float e2 = (s0 + 2 < len) ? __expf(x.z - m) : 0.f;
    float e3 = (s0 + 3 < len) ? __expf(x.w - m) : 0.f;
    float s = e0 + e1 + e2 + e3;
    #pragma unroll
    for (int o = 16; o > 0; o >>= 1) s += __shfl_xor_sync(0xffffffffu, s, o);
    if ((tid & 31) == 0) red_s[tid >> 5] = s;
    __syncthreads();
    if (tid < 32) {
        float ss = (tid < 8) ? red_s[tid] : 0.f;
        #pragma unroll
        for (int o = 4; o > 0; o >>= 1) ss += __shfl_xor_sync(0xffffffffu, ss, o);
        if (tid == 0) red_s[0] = ss;
    }
    __syncthreads();
    float inv = 1.0f / red_s[0];

    if (s0 < spad)
        ((float4*)p)[tid] = make_float4(e0 * inv, e1 * inv, e2 * inv, e3 * inv);
}

// ---------------------------------------------------------------------------
extern "C" void kernel_launch(void* const* d_in, const int* in_sizes, int n_in,
                              void* d_out, int out_size) {
    const float* ph   = (const float*)d_in[0];
    const float* g    = (const float*)d_in[1];
    const void*  lens = d_in[2];
    const float* Wk   = (const float*)d_in[3];
    const float* bk   = (const float*)d_in[4];
    const float* Wv   = (const float*)d_in[5];
    const float* bv   = (const float*)d_in[6];
    const float* Wq   = (const float*)d_in[7];
    const float* bq   = (const float*)d_in[8];
    const float* Wmel = (const float*)d_in[9];
    const float* bmel = (const float*)d_in[10];
    float* out = (float*)d_out;

    float* dkT;   cudaGetSymbolAddress((void**)&dkT,   g_kT);
    float* dv;    cudaGetSymbolAddress((void**)&dv,    g_v);
    float* dqT;   cudaGetSymbolAddress((void**)&dqT,   g_qT);
    float* datt;  cudaGetSymbolAddress((void**)&datt,  g_att);
    float* dvalT; cudaGetSymbolAddress((void**)&dvalT, g_valT);

    const float scale = 0.04419417382415922f;  // 1/sqrt(512)
    dim3 blk(256);

    // k projection -> kT [b][d][s] (EPI=5, TRIM=1)
    gemm_tf32<0,0,5,1><<<dim3(4, 128, 1), blk>>>(ph, DIM, 0, Wk, DIM, 0, bk,
                                                 dkT, 0, 0, DIM, 1.f, lens);
    // v projection -> v [b][s][d] (EPI=0, TRIM=1)
    gemm_tf32<0,0,0,1><<<dim3(4, 128, 1), blk>>>(ph, DIM, 0, Wv, DIM, 0, bv,
                                                 dv, DIM, 0, DIM, 1.f, lens);
    // q projection -> qT [b][d][t] (A_COL=1, EPI=4)
    gemm_tf32<1,0,4,0><<<dim3(4, 16, BATCH), blk>>>(g, SEQ_T, (long long)CF * SEQ_T,
                                                    Wq, DIM, 0, bq,
                                                    dqT, SEQ_T, (long long)DIM * SEQ_T,
                                                    CF, 1.f, lens);
    // scores: all-float4 paths (A_COL=1 qT, B_TR=0 kT), EPI=1, TRIM=2
    gemm_tf32<1,0,1,2><<<dim3(8, 16, BATCH), blk>>>(dqT, SEQ_T, (long long)DIM * SEQ_T,
                                                    dkT, SEQ_S, (long long)DIM * SEQ_S,
                                                    nullptr,
                                                    datt, SEQ_S, (long long)SEQ_T * SEQ_S,
                                                    DIM, scale, lens);
    softmax_kernel<<<BATCH * SEQ_T, 256>>>(lens);
    // value -> valT [b][d][t] (A_COL=0 att, B_TR=0 v, EPI=4 no bias, TRIM=3)
    gemm_tf32<0,0,4,3><<<dim3(4, 16, BATCH), blk>>>(datt, SEQ_S, (long long)SEQ_T * SEQ_S,
                                                    dv, DIM, (long long)SEQ_S * DIM,
                                                    nullptr,
                                                    dvalT, SEQ_T, (long long)DIM * SEQ_T,
                                                    SEQ_S, 1.f, lens);
    // mel: A_COL=1 valT, EPI=3 transposed out store
    gemm_tf32<1,0,3,0><<<dim3(10, 16, BATCH), blk>>>(dvalT, SEQ_T, (long long)DIM * SEQ_T,
                                                     Wmel, MELD, 0, bmel,
                                                     out, 0, 0, DIM, 1.f, lens);
}